// round 2
// baseline (speedup 1.0000x reference)
#include <cuda_runtime.h>
#include <cuda_bf16.h>

// Problem constants (GCN_48473000903499): N=50000, D=64, L=3, OUT=16, E=800000
#define NN   50000
#define DD   64
#define LL   3
#define OUTK 16
#define EE   800000
#define NE   (EE + NN)          // edges + self loops = 850000
#define NM   (NN * DD)          // 3,200,000 flat elements

// ---- scratch (device globals; no allocation allowed) ----
__device__ int   g_deg_out[NN];
__device__ int   g_deg_in[NN];
__device__ int   g_off[NN + 1];
__device__ int   g_cursor[NN];
__device__ int   g_csr_src[NE];
__device__ float g_norm_src[NN];
__device__ float g_norm_dst[NN];
__device__ float g_xa[NM];
__device__ float g_xb[NM];

// ---------------------------------------------------------------------------
// 1. init degrees to 1 (self loops)
__global__ void k_init_deg() {
    int i = blockIdx.x * blockDim.x + threadIdx.x;
    if (i < NN) { g_deg_out[i] = 1; g_deg_in[i] = 1; }
}

// 2. histogram edges
__global__ void k_hist(const int* __restrict__ src, const int* __restrict__ dst) {
    int e = blockIdx.x * blockDim.x + threadIdx.x;
    if (e < EE) {
        atomicAdd(&g_deg_out[src[e]], 1);
        atomicAdd(&g_deg_in[dst[e]], 1);
    }
}

// 3. norms
__global__ void k_norm() {
    int i = blockIdx.x * blockDim.x + threadIdx.x;
    if (i < NN) {
        g_norm_src[i] = rsqrtf((float)g_deg_out[i]);
        g_norm_dst[i] = rsqrtf((float)g_deg_in[i]);
    }
}

// 4. exclusive prefix scan of deg_in -> off, cursor (single block, 1024 thr)
__global__ void k_scan() {
    const int T = 1024;
    const int chunk = (NN + T - 1) / T;  // 49
    int t = threadIdx.x;
    int lo = t * chunk;
    int hi = lo + chunk; if (hi > NN) hi = NN;

    int sum = 0;
    for (int i = lo; i < hi; i++) sum += g_deg_in[i];

    // block exclusive scan of per-thread sums
    __shared__ int warp_sums[32];
    int lane = t & 31, w = t >> 5;
    int v = sum;
    #pragma unroll
    for (int s = 1; s < 32; s <<= 1) {
        int u = __shfl_up_sync(0xffffffffu, v, s);
        if (lane >= s) v += u;
    }
    if (lane == 31) warp_sums[w] = v;
    __syncthreads();
    if (w == 0) {
        int ws = warp_sums[lane];
        #pragma unroll
        for (int s = 1; s < 32; s <<= 1) {
            int u = __shfl_up_sync(0xffffffffu, ws, s);
            if (lane >= s) ws += u;
        }
        warp_sums[lane] = ws;
    }
    __syncthreads();
    int excl = v - sum + (w > 0 ? warp_sums[w - 1] : 0);

    int run = excl;
    for (int i = lo; i < hi; i++) {
        g_off[i] = run;
        g_cursor[i] = run;
        run += g_deg_in[i];
    }
    if (hi == NN) g_off[NN] = run;  // all tail threads write same total
}

// 5. scatter edges (+ self loops) into CSR by dst
__global__ void k_scatter(const int* __restrict__ src, const int* __restrict__ dst) {
    int i = blockIdx.x * blockDim.x + threadIdx.x;
    if (i < EE) {
        int d = dst[i];
        int p = atomicAdd(&g_cursor[d], 1);
        g_csr_src[p] = src[i];
    } else if (i < NE) {
        int n = i - EE;
        int p = atomicAdd(&g_cursor[n], 1);
        g_csr_src[p] = n;
    }
}

// 6. fused SpMM (gather, no atomics) + 64x64 GEMM + bias + relu
//    one warp per node; 8 nodes per 256-thread block; W in shared
__global__ void __launch_bounds__(256) k_layer(
    const float* __restrict__ x, const float* __restrict__ W,
    const float* __restrict__ b, float* __restrict__ y)
{
    __shared__ float Wsh[DD * DD];       // 16 KB
    __shared__ float agg[8][DD];         // 2 KB
    int tid = threadIdx.x;
    for (int i = tid; i < DD * DD; i += 256) Wsh[i] = W[i];
    __syncthreads();

    int warp = tid >> 5, lane = tid & 31;
    int node = blockIdx.x * 8 + warp;
    if (node >= NN) return;

    int s0 = g_off[node], s1 = g_off[node + 1];
    float ax = 0.f, ay = 0.f;
    for (int j = s0; j < s1; j++) {
        int s = g_csr_src[j];                       // warp-uniform
        float ns = g_norm_src[s];                   // warp-uniform (broadcast)
        float2 vv = *(const float2*)&x[s * DD + lane * 2];
        ax = fmaf(vv.x, ns, ax);
        ay = fmaf(vv.y, ns, ay);
    }
    float nd = g_norm_dst[node];
    ((float2*)&agg[warp][0])[lane] = make_float2(ax * nd, ay * nd);
    __syncwarp();

    int c0 = lane * 2;
    float o0 = b[c0], o1 = b[c0 + 1];
    #pragma unroll
    for (int k = 0; k < DD; k++) {
        float a = agg[warp][k];
        float2 wv = *(const float2*)&Wsh[k * DD + c0];
        o0 = fmaf(a, wv.x, o0);
        o1 = fmaf(a, wv.y, o1);
    }
    float2 out;
    out.x = fmaxf(o0, 0.f);
    out.y = fmaxf(o1, 0.f);
    *(float2*)&y[node * DD + c0] = out;
}

// 7. out = fc_b
__global__ void k_init_out(const float* __restrict__ fc_b, float* __restrict__ out) {
    int i = threadIdx.x;
    if (i < OUTK) out[i] = fc_b[i];
}

// 8. out += fc_w @ relu(flat)   (DRAM-streaming GEMV, 16 accumulators/thread)
__global__ void __launch_bounds__(256) k_fc(
    const float* __restrict__ fc_w, const float* __restrict__ xflat,
    float* __restrict__ out)
{
    __shared__ float sh[OUTK];
    if (threadIdx.x < OUTK) sh[threadIdx.x] = 0.f;
    __syncthreads();

    const int nv = NM / 4;  // 800000 float4s per output row
    float acc[OUTK];
    #pragma unroll
    for (int o = 0; o < OUTK; o++) acc[o] = 0.f;

    const float4* w4 = (const float4*)fc_w;
    const float4* x4 = (const float4*)xflat;
    int stride = gridDim.x * blockDim.x;
    for (int i = blockIdx.x * blockDim.x + threadIdx.x; i < nv; i += stride) {
        float4 f = x4[i];
        f.x = fmaxf(f.x, 0.f); f.y = fmaxf(f.y, 0.f);
        f.z = fmaxf(f.z, 0.f); f.w = fmaxf(f.w, 0.f);
        #pragma unroll
        for (int o = 0; o < OUTK; o++) {
            float4 w = __ldg(&w4[(size_t)o * nv + i]);
            acc[o] = fmaf(w.x, f.x, acc[o]);
            acc[o] = fmaf(w.y, f.y, acc[o]);
            acc[o] = fmaf(w.z, f.z, acc[o]);
            acc[o] = fmaf(w.w, f.w, acc[o]);
        }
    }

    #pragma unroll
    for (int o = 0; o < OUTK; o++) {
        float v = acc[o];
        #pragma unroll
        for (int s = 16; s; s >>= 1) v += __shfl_xor_sync(0xffffffffu, v, s);
        if ((threadIdx.x & 31) == 0) atomicAdd(&sh[o], v);
    }
    __syncthreads();
    if (threadIdx.x < OUTK) atomicAdd(&out[threadIdx.x], sh[threadIdx.x]);
}

// ---------------------------------------------------------------------------
extern "C" void kernel_launch(void* const* d_in, const int* in_sizes, int n_in,
                              void* d_out, int out_size)
{
    const float* F     = (const float*)d_in[0];
    const int*   src   = (const int*)d_in[1];
    const int*   dst   = (const int*)d_in[2];
    const float* gcn_w = (const float*)d_in[3];
    const float* gcn_b = (const float*)d_in[4];
    const float* fc_w  = (const float*)d_in[5];
    const float* fc_b  = (const float*)d_in[6];
    float* out = (float*)d_out;

    float* xa; float* xb;
    cudaGetSymbolAddress((void**)&xa, g_xa);
    cudaGetSymbolAddress((void**)&xb, g_xb);

    // graph prep
    k_init_deg<<<(NN + 255) / 256, 256>>>();
    k_hist<<<(EE + 255) / 256, 256>>>(src, dst);
    k_norm<<<(NN + 255) / 256, 256>>>();
    k_scan<<<1, 1024>>>();
    k_scatter<<<(NE + 255) / 256, 256>>>(src, dst);

    // 3 GCN layers: F -> xa -> xb -> xa
    const int lblocks = (NN + 7) / 8;
    k_layer<<<lblocks, 256>>>(F,  gcn_w + 0 * DD * DD, gcn_b + 0 * DD, xa);
    k_layer<<<lblocks, 256>>>(xa, gcn_w + 1 * DD * DD, gcn_b + 1 * DD, xb);
    k_layer<<<lblocks, 256>>>(xb, gcn_w + 2 * DD * DD, gcn_b + 2 * DD, xa);

    // FC head
    k_init_out<<<1, 32>>>(fc_b, out);
    k_fc<<<1184, 256>>>(fc_w, xa, out);
}

// round 3
// speedup vs baseline: 1.2570x; 1.2570x over previous
#include <cuda_runtime.h>
#include <cuda_bf16.h>

// Problem constants (GCN_48473000903499): N=50000, D=64, L=3, OUT=16, E=800000
#define NN   50000
#define DD   64
#define OUTK 16
#define EE   800000
#define NE   (EE + NN)          // edges + self loops = 850000
#define NM   (NN * DD)          // 3,200,000 flat elements
#define SCAN_B 1024             // elements per scan block
#define NBLK ((NN + SCAN_B - 1) / SCAN_B)   // 49

// ---- scratch (device globals; no allocation allowed) ----
__device__ int   g_deg_out[NN];
__device__ int   g_deg_in[NN];
__device__ int   g_off[NN + 1];
__device__ int   g_cursor[NN];
__device__ int   g_csr_src[NE];
__device__ int   g_bsum[NBLK];
__device__ int   g_boff[NBLK];
__device__ float g_norm_src[NN];
__device__ float g_norm_dst[NN];
__device__ float g_xa[NM];
__device__ float g_xb[NM];

// ---------------------------------------------------------------------------
// 1. init degrees to 1 (self loops)
__global__ void k_init_deg() {
    int i = blockIdx.x * blockDim.x + threadIdx.x;
    if (i < NN) { g_deg_out[i] = 1; g_deg_in[i] = 1; }
}

// 2. histogram edges
__global__ void k_hist(const int* __restrict__ src, const int* __restrict__ dst) {
    int e = blockIdx.x * blockDim.x + threadIdx.x;
    if (e < EE) {
        atomicAdd(&g_deg_out[src[e]], 1);
        atomicAdd(&g_deg_in[dst[e]], 1);
    }
}

// 3a. per-block exclusive scan of deg_in (1024 elems / 256-thread block)
__global__ void __launch_bounds__(256) k_scan1() {
    int blk = blockIdx.x, t = threadIdx.x;
    int base = blk * SCAN_B + t * 4;

    int v0 = 0, v1 = 0, v2 = 0, v3 = 0;
    if (base + 0 < NN) v0 = g_deg_in[base + 0];
    if (base + 1 < NN) v1 = g_deg_in[base + 1];
    if (base + 2 < NN) v2 = g_deg_in[base + 2];
    if (base + 3 < NN) v3 = g_deg_in[base + 3];
    int tsum = v0 + v1 + v2 + v3;

    __shared__ int warp_sums[8];
    int lane = t & 31, w = t >> 5;
    int inc = tsum;
    #pragma unroll
    for (int s = 1; s < 32; s <<= 1) {
        int u = __shfl_up_sync(0xffffffffu, inc, s);
        if (lane >= s) inc += u;
    }
    if (lane == 31) warp_sums[w] = inc;
    __syncthreads();
    if (t < 8) {
        int ws = warp_sums[t];
        #pragma unroll
        for (int s = 1; s < 8; s <<= 1) {
            int u = __shfl_up_sync(0xffu, ws, s);
            if (t >= s) ws += u;
        }
        warp_sums[t] = ws;
    }
    __syncthreads();
    int excl = inc - tsum + (w > 0 ? warp_sums[w - 1] : 0);

    if (base + 0 < NN) g_off[base + 0] = excl;
    if (base + 1 < NN) g_off[base + 1] = excl + v0;
    if (base + 2 < NN) g_off[base + 2] = excl + v0 + v1;
    if (base + 3 < NN) g_off[base + 3] = excl + v0 + v1 + v2;

    if (t == 255) g_bsum[blk] = excl + tsum;   // block total
}

// 3b. scan the 49 block sums (trivial serial)
__global__ void k_scan2() {
    int run = 0;
    #pragma unroll
    for (int b = 0; b < NBLK; b++) {
        g_boff[b] = run;
        run += g_bsum[b];
    }
    g_off[NN] = run;   // = NE
}

// 3c. add block offsets, init cursor, compute norms
__global__ void k_scan3() {
    int i = blockIdx.x * blockDim.x + threadIdx.x;
    if (i < NN) {
        int o = g_off[i] + g_boff[i / SCAN_B];
        g_off[i] = o;
        g_cursor[i] = o;
        g_norm_src[i] = rsqrtf((float)g_deg_out[i]);
        g_norm_dst[i] = rsqrtf((float)g_deg_in[i]);
    }
}

// 4. scatter edges (+ self loops) into CSR by dst
__global__ void k_scatter(const int* __restrict__ src, const int* __restrict__ dst) {
    int i = blockIdx.x * blockDim.x + threadIdx.x;
    if (i < EE) {
        int d = dst[i];
        int p = atomicAdd(&g_cursor[d], 1);
        g_csr_src[p] = src[i];
    } else if (i < NE) {
        int n = i - EE;
        int p = atomicAdd(&g_cursor[n], 1);
        g_csr_src[p] = n;
    }
}

// 5. premultiply F by norm_src (layer-0 input prep)
__global__ void k_premul(const float* __restrict__ F, float* __restrict__ h) {
    int i = blockIdx.x * blockDim.x + threadIdx.x;   // element index
    if (i < NM) h[i] = F[i] * g_norm_src[i >> 6];
}

// 6. fused SpMM (gather, src-norm pre-folded) + 64x64 GEMM + bias + relu
//    one warp per node; 8 nodes per 256-thread block; W in shared.
//    If PREMUL_OUT, output rows are pre-scaled by norm_src for the next layer.
template <bool PREMUL_OUT>
__global__ void __launch_bounds__(256) k_layer(
    const float* __restrict__ x, const float* __restrict__ W,
    const float* __restrict__ b, float* __restrict__ y)
{
    __shared__ float Wsh[DD * DD];       // 16 KB
    __shared__ float agg[8][DD];         // 2 KB
    int tid = threadIdx.x;
    for (int i = tid; i < DD * DD; i += 256) Wsh[i] = W[i];
    __syncthreads();

    int warp = tid >> 5, lane = tid & 31;
    int node = blockIdx.x * 8 + warp;
    if (node >= NN) return;

    int s0 = g_off[node], s1 = g_off[node + 1];
    float ax = 0.f, ay = 0.f;
    for (int base = s0; base < s1; base += 32) {
        int rem = s1 - base;
        int s = (lane < rem) ? g_csr_src[base + lane] : 0;
        int cnt = rem < 32 ? rem : 32;
        #pragma unroll 4
        for (int t = 0; t < cnt; t++) {
            int ss = __shfl_sync(0xffffffffu, s, t);
            float2 vv = *(const float2*)&x[ss * DD + lane * 2];
            ax += vv.x;
            ay += vv.y;
        }
    }
    float nd = g_norm_dst[node];
    ((float2*)&agg[warp][0])[lane] = make_float2(ax * nd, ay * nd);
    __syncwarp();

    int c0 = lane * 2;
    float o0 = b[c0], o1 = b[c0 + 1];
    #pragma unroll
    for (int k = 0; k < DD; k++) {
        float a = agg[warp][k];
        float2 wv = *(const float2*)&Wsh[k * DD + c0];
        o0 = fmaf(a, wv.x, o0);
        o1 = fmaf(a, wv.y, o1);
    }
    o0 = fmaxf(o0, 0.f);
    o1 = fmaxf(o1, 0.f);
    if (PREMUL_OUT) {
        float ns = g_norm_src[node];
        o0 *= ns; o1 *= ns;
    }
    *(float2*)&y[node * DD + c0] = make_float2(o0, o1);
}

// 7. out = fc_b
__global__ void k_init_out(const float* __restrict__ fc_b, float* __restrict__ out) {
    int i = threadIdx.x;
    if (i < OUTK) out[i] = fc_b[i];
}

// 8. out += fc_w @ relu(flat)   (DRAM-streaming GEMV, 16 accumulators/thread)
__global__ void __launch_bounds__(256) k_fc(
    const float* __restrict__ fc_w, const float* __restrict__ xflat,
    float* __restrict__ out)
{
    __shared__ float sh[OUTK];
    if (threadIdx.x < OUTK) sh[threadIdx.x] = 0.f;
    __syncthreads();

    const int nv = NM / 4;  // 800000 float4s per output row
    float acc[OUTK];
    #pragma unroll
    for (int o = 0; o < OUTK; o++) acc[o] = 0.f;

    const float4* w4 = (const float4*)fc_w;
    const float4* x4 = (const float4*)xflat;
    int stride = gridDim.x * blockDim.x;
    for (int i = blockIdx.x * blockDim.x + threadIdx.x; i < nv; i += stride) {
        float4 f = x4[i];
        f.x = fmaxf(f.x, 0.f); f.y = fmaxf(f.y, 0.f);
        f.z = fmaxf(f.z, 0.f); f.w = fmaxf(f.w, 0.f);
        #pragma unroll
        for (int o = 0; o < OUTK; o++) {
            float4 w = __ldg(&w4[(size_t)o * nv + i]);
            acc[o] = fmaf(w.x, f.x, acc[o]);
            acc[o] = fmaf(w.y, f.y, acc[o]);
            acc[o] = fmaf(w.z, f.z, acc[o]);
            acc[o] = fmaf(w.w, f.w, acc[o]);
        }
    }

    #pragma unroll
    for (int o = 0; o < OUTK; o++) {
        float v = acc[o];
        #pragma unroll
        for (int s = 16; s; s >>= 1) v += __shfl_xor_sync(0xffffffffu, v, s);
        if ((threadIdx.x & 31) == 0) atomicAdd(&sh[o], v);
    }
    __syncthreads();
    if (threadIdx.x < OUTK) atomicAdd(&out[threadIdx.x], sh[threadIdx.x]);
}

// ---------------------------------------------------------------------------
extern "C" void kernel_launch(void* const* d_in, const int* in_sizes, int n_in,
                              void* d_out, int out_size)
{
    const float* F     = (const float*)d_in[0];
    const int*   src   = (const int*)d_in[1];
    const int*   dst   = (const int*)d_in[2];
    const float* gcn_w = (const float*)d_in[3];
    const float* gcn_b = (const float*)d_in[4];
    const float* fc_w  = (const float*)d_in[5];
    const float* fc_b  = (const float*)d_in[6];
    float* out = (float*)d_out;

    float* xa; float* xb;
    cudaGetSymbolAddress((void**)&xa, g_xa);
    cudaGetSymbolAddress((void**)&xb, g_xb);

    // graph prep
    k_init_deg<<<(NN + 255) / 256, 256>>>();
    k_hist<<<(EE + 255) / 256, 256>>>(src, dst);
    k_scan1<<<NBLK, 256>>>();
    k_scan2<<<1, 1>>>();
    k_scan3<<<(NN + 255) / 256, 256>>>();
    k_scatter<<<(NE + 255) / 256, 256>>>(src, dst);

    // layer-0 input: F * norm_src
    k_premul<<<(NM + 255) / 256, 256>>>(F, xa);

    // 3 GCN layers: xa -> xb -> xa -> xb  (first two pre-scale by norm_src)
    const int lblocks = (NN + 7) / 8;
    k_layer<true ><<<lblocks, 256>>>(xa, gcn_w + 0 * DD * DD, gcn_b + 0 * DD, xb);
    k_layer<true ><<<lblocks, 256>>>(xb, gcn_w + 1 * DD * DD, gcn_b + 1 * DD, xa);
    k_layer<false><<<lblocks, 256>>>(xa, gcn_w + 2 * DD * DD, gcn_b + 2 * DD, xb);

    // FC head
    k_init_out<<<1, 32>>>(fc_b, out);
    k_fc<<<1184, 256>>>(fc_w, xb, out);
}

// round 4
// speedup vs baseline: 1.3546x; 1.0776x over previous
#include <cuda_runtime.h>
#include <cuda_fp16.h>

// Problem constants (GCN_48473000903499): N=50000, D=64, L=3, OUT=16, E=800000
#define NN   50000
#define DD   64
#define OUTK 16
#define EE   800000
#define NE   (EE + NN)          // edges + self loops = 850000
#define NM   (NN * DD)          // 3,200,000 flat elements
#define NH2  (NM / 2)           // half2 count per feature buffer

// ---- scratch (device globals; no allocation allowed) ----
// g_ints layout: [0,NN) deg_out(edges only), [NN,2NN) deg_in(edges only), [2NN] alloc counter
__device__ int     g_ints[2 * NN + 1];
__device__ int     g_off[NN];
__device__ int     g_cursor[NN];
__device__ int     g_csr_src[NE];
__device__ float   g_norm_src[NN];
__device__ float   g_norm_dst[NN];
__device__ __half2 g_ha[NH2];      // fp16 feature ping
__device__ __half2 g_hb[NH2];      // fp16 feature pong
__device__ float   g_xf[NM];       // final-layer fp32 output (FC input)

// ---------------------------------------------------------------------------
// 1. histogram edges (deg arrays pre-zeroed by memset; self loop added later)
__global__ void k_hist(const int* __restrict__ src, const int* __restrict__ dst) {
    int e = blockIdx.x * blockDim.x + threadIdx.x;
    if (e < EE) {
        atomicAdd(&g_ints[src[e]], 1);          // deg_out
        atomicAdd(&g_ints[NN + dst[e]], 1);     // deg_in
    }
}

// 2. per-node: norms (+1 for self loop), CSR slot allocation via atomic counter,
//    and FC-output bias init (replaces the ordered prefix scan entirely)
__global__ void k_build(const float* __restrict__ fc_b, float* __restrict__ out) {
    int i = blockIdx.x * blockDim.x + threadIdx.x;
    if (i < NN) {
        int dout = g_ints[i] + 1;
        int din  = g_ints[NN + i] + 1;
        g_norm_src[i] = rsqrtf((float)dout);
        g_norm_dst[i] = rsqrtf((float)din);
        int off = atomicAdd(&g_ints[2 * NN], din);
        g_off[i] = off;
        g_cursor[i] = off;
    }
    if (blockIdx.x == 0 && threadIdx.x < OUTK) out[threadIdx.x] = fc_b[threadIdx.x];
}

// 3. scatter edges (+ self loops) into CSR by dst
__global__ void k_scatter(const int* __restrict__ src, const int* __restrict__ dst) {
    int i = blockIdx.x * blockDim.x + threadIdx.x;
    if (i < EE) {
        int d = dst[i];
        int p = atomicAdd(&g_cursor[d], 1);
        g_csr_src[p] = src[i];
    } else if (i < NE) {
        int n = i - EE;
        int p = atomicAdd(&g_cursor[n], 1);
        g_csr_src[p] = n;
    }
}

// 4. layer-0 input prep: h = F * norm_src, stored fp16 (2 elems/thread)
__global__ void k_premul(const float* __restrict__ F) {
    int j = blockIdx.x * blockDim.x + threadIdx.x;   // half2 index
    if (j < NH2) {
        float2 f = ((const float2*)F)[j];
        float ns = g_norm_src[j >> 5];               // node = (2j)/64
        g_ha[j] = __floats2half2_rn(f.x * ns, f.y * ns);
    }
}

// 5. fused SpMM gather (fp16 rows, src-norm pre-folded) + 64x64 GEMM + bias + relu
//    one warp per node, 8 nodes per block, W fp32 in shared.
//    HALF_OUT: write fp16 pre-scaled by norm_src (feeds next layer's gather);
//    else write fp32 (feeds FC).
template <bool HALF_OUT>
__global__ void __launch_bounds__(256) k_layer(
    const __half2* __restrict__ x2, const float* __restrict__ W,
    const float* __restrict__ b, __half2* __restrict__ yh, float* __restrict__ yf)
{
    __shared__ float Wsh[DD * DD];       // 16 KB
    __shared__ float agg[8][DD];         // 2 KB
    int tid = threadIdx.x;
    for (int i = tid; i < DD * DD; i += 256) Wsh[i] = W[i];
    __syncthreads();

    int warp = tid >> 5, lane = tid & 31;
    int node = blockIdx.x * 8 + warp;
    if (node >= NN) return;

    int s0 = g_off[node];
    int s1 = s0 + g_ints[NN + node] + 1;   // deg_in + self loop

    float ax = 0.f, ay = 0.f;
    for (int base = s0; base < s1; base += 32) {
        int rem = s1 - base;
        int s = (lane < rem) ? g_csr_src[base + lane] : 0;
        int cnt = rem < 32 ? rem : 32;
        #pragma unroll 4
        for (int t = 0; t < cnt; t++) {
            int ss = __shfl_sync(0xffffffffu, s, t);
            float2 v = __half22float2(x2[ss * 32 + lane]);
            ax += v.x;
            ay += v.y;
        }
    }
    float nd = g_norm_dst[node];
    ((float2*)&agg[warp][0])[lane] = make_float2(ax * nd, ay * nd);
    __syncwarp();

    int c0 = lane * 2;
    float o0 = b[c0], o1 = b[c0 + 1];
    #pragma unroll
    for (int k = 0; k < DD; k++) {
        float a = agg[warp][k];
        float2 wv = *(const float2*)&Wsh[k * DD + c0];
        o0 = fmaf(a, wv.x, o0);
        o1 = fmaf(a, wv.y, o1);
    }
    o0 = fmaxf(o0, 0.f);
    o1 = fmaxf(o1, 0.f);

    if (HALF_OUT) {
        float ns = g_norm_src[node];
        yh[node * 32 + lane] = __floats2half2_rn(o0 * ns, o1 * ns);
    } else {
        *(float2*)&yf[node * DD + c0] = make_float2(o0, o1);
    }
}

// 6. out += fc_w @ relu(flat)   (DRAM-streaming GEMV, 16 accumulators/thread)
__global__ void __launch_bounds__(256) k_fc(
    const float* __restrict__ fc_w, const float* __restrict__ xflat,
    float* __restrict__ out)
{
    __shared__ float sh[OUTK];
    if (threadIdx.x < OUTK) sh[threadIdx.x] = 0.f;
    __syncthreads();

    const int nv = NM / 4;  // 800000 float4s per output row
    float acc[OUTK];
    #pragma unroll
    for (int o = 0; o < OUTK; o++) acc[o] = 0.f;

    const float4* w4 = (const float4*)fc_w;
    const float4* x4 = (const float4*)xflat;
    int stride = gridDim.x * blockDim.x;
    for (int i = blockIdx.x * blockDim.x + threadIdx.x; i < nv; i += stride) {
        float4 f = x4[i];
        f.x = fmaxf(f.x, 0.f); f.y = fmaxf(f.y, 0.f);
        f.z = fmaxf(f.z, 0.f); f.w = fmaxf(f.w, 0.f);
        #pragma unroll
        for (int o = 0; o < OUTK; o++) {
            float4 w = __ldg(&w4[(size_t)o * nv + i]);
            acc[o] = fmaf(w.x, f.x, acc[o]);
            acc[o] = fmaf(w.y, f.y, acc[o]);
            acc[o] = fmaf(w.z, f.z, acc[o]);
            acc[o] = fmaf(w.w, f.w, acc[o]);
        }
    }

    #pragma unroll
    for (int o = 0; o < OUTK; o++) {
        float v = acc[o];
        #pragma unroll
        for (int s = 16; s; s >>= 1) v += __shfl_xor_sync(0xffffffffu, v, s);
        if ((threadIdx.x & 31) == 0) atomicAdd(&sh[o], v);
    }
    __syncthreads();
    if (threadIdx.x < OUTK) atomicAdd(&out[threadIdx.x], sh[threadIdx.x]);
}

// ---------------------------------------------------------------------------
extern "C" void kernel_launch(void* const* d_in, const int* in_sizes, int n_in,
                              void* d_out, int out_size)
{
    const float* F     = (const float*)d_in[0];
    const int*   src   = (const int*)d_in[1];
    const int*   dst   = (const int*)d_in[2];
    const float* gcn_w = (const float*)d_in[3];
    const float* gcn_b = (const float*)d_in[4];
    const float* fc_w  = (const float*)d_in[5];
    const float* fc_b  = (const float*)d_in[6];
    float* out = (float*)d_out;

    void* ints_addr;   cudaGetSymbolAddress(&ints_addr, g_ints);
    __half2* ha; cudaGetSymbolAddress((void**)&ha, g_ha);
    __half2* hb; cudaGetSymbolAddress((void**)&hb, g_hb);
    float*   xf; cudaGetSymbolAddress((void**)&xf, g_xf);

    // graph prep
    cudaMemsetAsync(ints_addr, 0, (2 * NN + 1) * sizeof(int));
    k_hist<<<(EE + 255) / 256, 256>>>(src, dst);
    k_build<<<(NN + 255) / 256, 256>>>(fc_b, out);
    k_scatter<<<(NE + 255) / 256, 256>>>(src, dst);

    // layer-0 input: F * norm_src -> fp16
    k_premul<<<(NH2 + 255) / 256, 256>>>(F);

    // 3 GCN layers: ha -> hb -> ha -> xf (fp32)
    const int lblocks = (NN + 7) / 8;
    k_layer<true ><<<lblocks, 256>>>(ha, gcn_w + 0 * DD * DD, gcn_b + 0 * DD, hb, nullptr);
    k_layer<true ><<<lblocks, 256>>>(hb, gcn_w + 1 * DD * DD, gcn_b + 1 * DD, ha, nullptr);
    k_layer<false><<<lblocks, 256>>>(ha, gcn_w + 2 * DD * DD, gcn_b + 2 * DD, nullptr, xf);

    // FC head
    k_fc<<<1184, 256>>>(fc_w, xf, out);
}

// round 5
// speedup vs baseline: 1.4393x; 1.0626x over previous
#include <cuda_runtime.h>
#include <cuda_fp16.h>

// Problem constants (GCN_48473000903499): N=50000, D=64, L=3, OUT=16, E=800000
#define NN   50000
#define DD   64
#define OUTK 16
#define EE   800000
#define NE   (EE + NN)            // edges + self loops = 850000
#define NEP  (NE + 7 * NN)        // CSR capacity with per-row pad-to-8
#define NM   (NN * DD)            // 3,200,000 flat elements
#define NH2  (NN * 32)            // half2 count of real rows
#define NH2P ((NN + 1) * 32)      // + one zero pad row (index NN)

// ---- scratch (device globals; no allocation allowed) ----
// g_ints: [0,NN) deg_out(edges), [NN,2NN) deg_in(edges)->padded row len, [2NN] alloc counter
__device__ int     g_ints[2 * NN + 1];
__device__ int     g_off[NN];
__device__ int     g_cursor[NN];
__device__ int     g_csr_src[NEP];
__device__ float   g_norm_src[NN];
__device__ float   g_norm_dst[NN];
__device__ __half2 g_ha[NH2P];     // fp16 feature ping (row NN = zeros)
__device__ __half2 g_hb[NH2P];     // fp16 feature pong (row NN = zeros)
__device__ float   g_xf[NM];       // final-layer fp32 output (FC input)

// ---------------------------------------------------------------------------
// 1. histogram edges (deg arrays pre-zeroed by memset)
__global__ void k_hist(const int* __restrict__ src, const int* __restrict__ dst) {
    int e = blockIdx.x * blockDim.x + threadIdx.x;
    if (e < EE) {
        atomicAdd(&g_ints[src[e]], 1);          // deg_out
        atomicAdd(&g_ints[NN + dst[e]], 1);     // deg_in
    }
}

// 2. per-node: norms (+1 self loop), padded CSR slot alloc, pad-fill with zero-row
//    index NN, bias init, and zero the pad feature rows.
__global__ void k_build(const float* __restrict__ fc_b, float* __restrict__ out) {
    int i = blockIdx.x * blockDim.x + threadIdx.x;
    if (i < NN) {
        int dout = g_ints[i] + 1;
        int din  = g_ints[NN + i] + 1;          // entries incl. self loop
        g_norm_src[i] = rsqrtf((float)dout);
        g_norm_dst[i] = rsqrtf((float)din);
        int dpad = (din + 7) & ~7;
        int off = atomicAdd(&g_ints[2 * NN], dpad);
        g_off[i] = off;
        g_cursor[i] = off;
        g_ints[NN + i] = dpad;                  // repurpose: padded row length
        for (int p = off + din; p < off + dpad; p++) g_csr_src[p] = NN;
    }
    if (blockIdx.x == 0) {
        if (threadIdx.x < OUTK) out[threadIdx.x] = fc_b[threadIdx.x];
        if (threadIdx.x >= 32 && threadIdx.x < 64) {   // zero pad rows
            int l = threadIdx.x - 32;
            g_ha[NN * 32 + l] = __floats2half2_rn(0.f, 0.f);
            g_hb[NN * 32 + l] = __floats2half2_rn(0.f, 0.f);
        }
    }
}

// 3. fused: scatter edges+loops into CSR, and premul F*norm_src -> fp16 ha
__global__ void k_scatpre(const int* __restrict__ src, const int* __restrict__ dst,
                          const float* __restrict__ F) {
    int i = blockIdx.x * blockDim.x + threadIdx.x;
    if (i < NE) {
        if (i < EE) {
            int d = dst[i];
            int p = atomicAdd(&g_cursor[d], 1);
            g_csr_src[p] = src[i];
        } else {
            int n = i - EE;
            int p = atomicAdd(&g_cursor[n], 1);
            g_csr_src[p] = n;
        }
    } else {
        int j = i - NE;                         // half2 index
        if (j < NH2) {
            float2 f = ((const float2*)F)[j];
            float ns = g_norm_src[j >> 5];
            g_ha[j] = __floats2half2_rn(f.x * ns, f.y * ns);
        }
    }
}

// 4. fused SpMM gather (fp16 rows, src-norm pre-folded) + 64x64 GEMM + bias + relu
//    4 nodes per warp, 8 warps/block (32 nodes/block); W+b in shared, loaded once.
//    CSR rows padded to x8 -> branch-free batches of 8 independent loads (MLP=8).
template <bool HALF_OUT>
__global__ void __launch_bounds__(256) k_layer(
    const __half2* __restrict__ x2, const float* __restrict__ W,
    const float* __restrict__ b, __half2* __restrict__ yh, float* __restrict__ yf)
{
    __shared__ float Wsh[DD * DD];       // 16 KB
    __shared__ float bsh[DD];
    __shared__ float agg[8][DD];         // 2 KB
    int tid = threadIdx.x;
    for (int i = tid; i < DD * DD; i += 256) Wsh[i] = W[i];
    if (tid < DD) bsh[tid] = b[tid];
    __syncthreads();

    int warp = tid >> 5, lane = tid & 31;
    int c0 = lane * 2;

    #pragma unroll
    for (int it = 0; it < 4; it++) {
        int node = blockIdx.x * 32 + it * 8 + warp;
        if (node >= NN) continue;

        int s0 = g_off[node];
        int s1 = s0 + g_ints[NN + node];        // padded length (multiple of 8)

        float ax = 0.f, ay = 0.f;
        for (int base = s0; base < s1; base += 32) {
            int rem = s1 - base;
            int s = (lane < rem) ? g_csr_src[base + lane] : NN;
            int nb = (rem < 32 ? rem : 32) >> 3;
            for (int q = 0; q < nb; q++) {
                float2 vv[8];
                #pragma unroll
                for (int t = 0; t < 8; t++) {
                    int ss = __shfl_sync(0xffffffffu, s, q * 8 + t);
                    vv[t] = __half22float2(x2[ss * 32 + lane]);
                }
                #pragma unroll
                for (int t = 0; t < 8; t++) { ax += vv[t].x; ay += vv[t].y; }
            }
        }
        float nd = g_norm_dst[node];
        ((float2*)&agg[warp][0])[lane] = make_float2(ax * nd, ay * nd);
        __syncwarp();

        float o0 = bsh[c0], o1 = bsh[c0 + 1];
        #pragma unroll
        for (int k = 0; k < DD; k++) {
            float a = agg[warp][k];
            float2 wv = *(const float2*)&Wsh[k * DD + c0];
            o0 = fmaf(a, wv.x, o0);
            o1 = fmaf(a, wv.y, o1);
        }
        o0 = fmaxf(o0, 0.f);
        o1 = fmaxf(o1, 0.f);

        if (HALF_OUT) {
            float ns = g_norm_src[node];
            yh[node * 32 + lane] = __floats2half2_rn(o0 * ns, o1 * ns);
        } else {
            *(float2*)&yf[node * DD + c0] = make_float2(o0, o1);
        }
        __syncwarp();
    }
}

// 5. out += fc_w @ relu(flat)   (DRAM-streaming GEMV, 16 accumulators/thread)
__global__ void __launch_bounds__(256) k_fc(
    const float* __restrict__ fc_w, const float* __restrict__ xflat,
    float* __restrict__ out)
{
    __shared__ float sh[OUTK];
    if (threadIdx.x < OUTK) sh[threadIdx.x] = 0.f;
    __syncthreads();

    const int nv = NM / 4;  // 800000 float4s per output row
    float acc[OUTK];
    #pragma unroll
    for (int o = 0; o < OUTK; o++) acc[o] = 0.f;

    const float4* w4 = (const float4*)fc_w;
    const float4* x4 = (const float4*)xflat;
    int stride = gridDim.x * blockDim.x;
    for (int i = blockIdx.x * blockDim.x + threadIdx.x; i < nv; i += stride) {
        float4 f = x4[i];
        f.x = fmaxf(f.x, 0.f); f.y = fmaxf(f.y, 0.f);
        f.z = fmaxf(f.z, 0.f); f.w = fmaxf(f.w, 0.f);
        #pragma unroll
        for (int o = 0; o < OUTK; o++) {
            float4 w = __ldg(&w4[(size_t)o * nv + i]);
            acc[o] = fmaf(w.x, f.x, acc[o]);
            acc[o] = fmaf(w.y, f.y, acc[o]);
            acc[o] = fmaf(w.z, f.z, acc[o]);
            acc[o] = fmaf(w.w, f.w, acc[o]);
        }
    }

    #pragma unroll
    for (int o = 0; o < OUTK; o++) {
        float v = acc[o];
        #pragma unroll
        for (int s = 16; s; s >>= 1) v += __shfl_xor_sync(0xffffffffu, v, s);
        if ((threadIdx.x & 31) == 0) atomicAdd(&sh[o], v);
    }
    __syncthreads();
    if (threadIdx.x < OUTK) atomicAdd(&out[threadIdx.x], sh[threadIdx.x]);
}

// ---------------------------------------------------------------------------
extern "C" void kernel_launch(void* const* d_in, const int* in_sizes, int n_in,
                              void* d_out, int out_size)
{
    const float* F     = (const float*)d_in[0];
    const int*   src   = (const int*)d_in[1];
    const int*   dst   = (const int*)d_in[2];
    const float* gcn_w = (const float*)d_in[3];
    const float* gcn_b = (const float*)d_in[4];
    const float* fc_w  = (const float*)d_in[5];
    const float* fc_b  = (const float*)d_in[6];
    float* out = (float*)d_out;

    void* ints_addr;   cudaGetSymbolAddress(&ints_addr, g_ints);
    __half2* ha; cudaGetSymbolAddress((void**)&ha, g_ha);
    __half2* hb; cudaGetSymbolAddress((void**)&hb, g_hb);
    float*   xf; cudaGetSymbolAddress((void**)&xf, g_xf);

    // graph prep
    cudaMemsetAsync(ints_addr, 0, (2 * NN + 1) * sizeof(int));
    k_hist<<<(EE + 255) / 256, 256>>>(src, dst);
    k_build<<<(NN + 255) / 256, 256>>>(fc_b, out);
    k_scatpre<<<(NE + NH2 + 255) / 256, 256>>>(src, dst, F);

    // 3 GCN layers: ha -> hb -> ha -> xf (fp32); layer0 is 4th launch (ncu target)
    const int lblocks = (NN + 31) / 32;
    k_layer<true ><<<lblocks, 256>>>(ha, gcn_w + 0 * DD * DD, gcn_b + 0 * DD, hb, nullptr);
    k_layer<true ><<<lblocks, 256>>>(hb, gcn_w + 1 * DD * DD, gcn_b + 1 * DD, ha, nullptr);
    k_layer<false><<<lblocks, 256>>>(ha, gcn_w + 2 * DD * DD, gcn_b + 2 * DD, nullptr, xf);

    // FC head
    k_fc<<<1563, 256>>>(fc_w, xf, out);
}

// round 6
// speedup vs baseline: 1.8375x; 1.2766x over previous
#include <cuda_runtime.h>
#include <cuda_fp16.h>
#include <mma.h>

using namespace nvcuda;

// Problem constants (GCN_48473000903499): N=50000, D=64, L=3, OUT=16, E=800000
#define NN   50000
#define DD   64
#define OUTK 16
#define EE   800000
#define NE   (EE + NN)            // edges + self loops = 850000
#define NEP  (NE + 7 * NN)        // CSR capacity with per-row pad-to-8
#define NM   (NN * DD)            // 3,200,000 flat elements
#define NH2  (NN * 32)            // half2 count of real rows
#define NH2P ((NN + 1) * 32)      // + one zero pad row (index NN)
#define LDS_PAD 72                // smem row stride (halves / floats)

// ---- scratch (device globals; no allocation allowed) ----
// g_ints: [0,NN) deg_out(edges), [NN,2NN) deg_in(edges)->padded row len, [2NN] alloc counter
__device__ int     g_ints[2 * NN + 1];
__device__ int     g_off[NN];
__device__ int     g_cursor[NN];
__device__ int     g_csr_src[NEP];
__device__ float   g_norm_src[NN];
__device__ float   g_norm_dst[NN];
__device__ __half2 g_ha[NH2P];     // fp16 feature ping (row NN = zeros)
__device__ __half2 g_hb[NH2P];     // fp16 feature pong (row NN = zeros)
__device__ float   g_xf[NM];       // final-layer fp32 output (FC input)

// ---------------------------------------------------------------------------
// 1. histogram edges (deg arrays pre-zeroed by memset)
__global__ void k_hist(const int* __restrict__ src, const int* __restrict__ dst) {
    int e = blockIdx.x * blockDim.x + threadIdx.x;
    if (e < EE) {
        atomicAdd(&g_ints[src[e]], 1);          // deg_out
        atomicAdd(&g_ints[NN + dst[e]], 1);     // deg_in
    }
}

// 2. per-node: norms (+1 self loop), padded CSR slot alloc, pad-fill with zero-row
//    index NN, bias init, and zero the pad feature rows.
__global__ void k_build(const float* __restrict__ fc_b, float* __restrict__ out) {
    int i = blockIdx.x * blockDim.x + threadIdx.x;
    if (i < NN) {
        int dout = g_ints[i] + 1;
        int din  = g_ints[NN + i] + 1;          // entries incl. self loop
        g_norm_src[i] = rsqrtf((float)dout);
        g_norm_dst[i] = rsqrtf((float)din);
        int dpad = (din + 7) & ~7;
        int off = atomicAdd(&g_ints[2 * NN], dpad);
        g_off[i] = off;
        g_cursor[i] = off;
        g_ints[NN + i] = dpad;                  // repurpose: padded row length
        for (int p = off + din; p < off + dpad; p++) g_csr_src[p] = NN;
    }
    if (blockIdx.x == 0) {
        if (threadIdx.x < OUTK) out[threadIdx.x] = fc_b[threadIdx.x];
        if (threadIdx.x >= 32 && threadIdx.x < 64) {   // zero pad rows
            int l = threadIdx.x - 32;
            g_ha[NN * 32 + l] = __floats2half2_rn(0.f, 0.f);
            g_hb[NN * 32 + l] = __floats2half2_rn(0.f, 0.f);
        }
    }
}

// 3. fused: scatter edges+loops into CSR, and premul F*norm_src -> fp16 ha
__global__ void k_scatpre(const int* __restrict__ src, const int* __restrict__ dst,
                          const float* __restrict__ F) {
    int i = blockIdx.x * blockDim.x + threadIdx.x;
    if (i < NE) {
        if (i < EE) {
            int d = dst[i];
            int p = atomicAdd(&g_cursor[d], 1);
            g_csr_src[p] = src[i];
        } else {
            int n = i - EE;
            int p = atomicAdd(&g_cursor[n], 1);
            g_csr_src[p] = n;
        }
    } else {
        int j = i - NE;                         // half2 index
        if (j < NH2) {
            float2 f = ((const float2*)F)[j];
            float ns = g_norm_src[j >> 5];
            g_ha[j] = __floats2half2_rn(f.x * ns, f.y * ns);
        }
    }
}

// 4. fused SpMM gather + HMMA GEMM + bias + relu. 64 nodes per block, 8 warps.
//    Phase A: each warp gathers 8 nodes -> fp16 agg tile in smem (dst-norm applied)
//    Phase B: 64x64x64 GEMM via wmma (W fp16 in smem, fp32 accum)
//    Phase C: bias + relu (+ src-norm premul) epilogue
template <bool HALF_OUT>
__global__ void __launch_bounds__(256) k_layer(
    const __half2* __restrict__ x2, const float* __restrict__ W,
    const float* __restrict__ b, __half2* __restrict__ yh, float* __restrict__ yf)
{
    __shared__ __half Wh[DD][LDS_PAD];        // 9216 B
    __shared__ __half aggh[DD][LDS_PAD];      // 9216 B
    __shared__ float  outS[DD][LDS_PAD];      // 18432 B
    __shared__ float  bsh[DD];

    int tid = threadIdx.x;
    int warp = tid >> 5, lane = tid & 31;
    int nodeBase = blockIdx.x * 64;

    for (int i = tid; i < DD * DD; i += 256)
        Wh[i >> 6][i & 63] = __float2half(W[i]);
    if (tid < DD) bsh[tid] = b[tid];
    __syncthreads();

    // ---- Phase A: gather ----
    #pragma unroll 1
    for (int it = 0; it < 8; it++) {
        int local = warp * 8 + it;
        int node = nodeBase + local;
        float ax = 0.f, ay = 0.f;
        if (node < NN) {
            int s0 = g_off[node];
            int s1 = s0 + g_ints[NN + node];    // padded length (multiple of 8)
            for (int base = s0; base < s1; base += 32) {
                int rem = s1 - base;
                int s = (lane < rem) ? g_csr_src[base + lane] : NN;
                int nb = (rem < 32 ? rem : 32) >> 3;
                for (int q = 0; q < nb; q++) {
                    float2 vv[8];
                    #pragma unroll
                    for (int t = 0; t < 8; t++) {
                        int ss = __shfl_sync(0xffffffffu, s, q * 8 + t);
                        vv[t] = __half22float2(x2[ss * 32 + lane]);
                    }
                    #pragma unroll
                    for (int t = 0; t < 8; t++) { ax += vv[t].x; ay += vv[t].y; }
                }
            }
            float nd = g_norm_dst[node];
            ax *= nd; ay *= nd;
        }
        *(__half2*)&aggh[local][lane * 2] = __floats2half2_rn(ax, ay);
    }
    __syncthreads();

    // ---- Phase B: 64x64x64 GEMM via HMMA ----
    {
        int mi = warp >> 1;                // m-strip 0..3 (16 rows each)
        int n0 = (warp & 1) * 2;           // n-tile pair: tiles n0, n0+1

        wmma::fragment<wmma::matrix_a, 16, 16, 16, __half, wmma::row_major> aF[4];
        #pragma unroll
        for (int k = 0; k < 4; k++)
            wmma::load_matrix_sync(aF[k], &aggh[mi * 16][k * 16], LDS_PAD);

        #pragma unroll
        for (int nt = 0; nt < 2; nt++) {
            wmma::fragment<wmma::accumulator, 16, 16, 16, float> cF;
            wmma::fill_fragment(cF, 0.f);
            #pragma unroll
            for (int k = 0; k < 4; k++) {
                wmma::fragment<wmma::matrix_b, 16, 16, 16, __half, wmma::row_major> bF;
                wmma::load_matrix_sync(bF, &Wh[k * 16][(n0 + nt) * 16], LDS_PAD);
                wmma::mma_sync(cF, aF[k], bF, cF);
            }
            wmma::store_matrix_sync(&outS[mi * 16][(n0 + nt) * 16], cF, LDS_PAD,
                                    wmma::mem_row_major);
        }
    }
    __syncthreads();

    // ---- Phase C: epilogue ----
    int c0 = lane * 2;
    #pragma unroll 1
    for (int r = warp * 8; r < warp * 8 + 8; r++) {
        int node = nodeBase + r;
        if (node >= NN) break;
        float o0 = fmaxf(outS[r][c0]     + bsh[c0],     0.f);
        float o1 = fmaxf(outS[r][c0 + 1] + bsh[c0 + 1], 0.f);
        if (HALF_OUT) {
            float ns = g_norm_src[node];
            yh[node * 32 + lane] = __floats2half2_rn(o0 * ns, o1 * ns);
        } else {
            *(float2*)&yf[node * DD + c0] = make_float2(o0, o1);
        }
    }
}

// 5. out += fc_w @ relu(flat)   (DRAM-streaming GEMV, 16 accumulators/thread)
__global__ void __launch_bounds__(256) k_fc(
    const float* __restrict__ fc_w, const float* __restrict__ xflat,
    float* __restrict__ out)
{
    __shared__ float sh[OUTK];
    if (threadIdx.x < OUTK) sh[threadIdx.x] = 0.f;
    __syncthreads();

    const int nv = NM / 4;  // 800000 float4s per output row
    float acc[OUTK];
    #pragma unroll
    for (int o = 0; o < OUTK; o++) acc[o] = 0.f;

    const float4* w4 = (const float4*)fc_w;
    const float4* x4 = (const float4*)xflat;
    int stride = gridDim.x * blockDim.x;
    for (int i = blockIdx.x * blockDim.x + threadIdx.x; i < nv; i += stride) {
        float4 f = x4[i];
        f.x = fmaxf(f.x, 0.f); f.y = fmaxf(f.y, 0.f);
        f.z = fmaxf(f.z, 0.f); f.w = fmaxf(f.w, 0.f);
        #pragma unroll
        for (int o = 0; o < OUTK; o++) {
            float4 w = __ldg(&w4[(size_t)o * nv + i]);
            acc[o] = fmaf(w.x, f.x, acc[o]);
            acc[o] = fmaf(w.y, f.y, acc[o]);
            acc[o] = fmaf(w.z, f.z, acc[o]);
            acc[o] = fmaf(w.w, f.w, acc[o]);
        }
    }

    #pragma unroll
    for (int o = 0; o < OUTK; o++) {
        float v = acc[o];
        #pragma unroll
        for (int s = 16; s; s >>= 1) v += __shfl_xor_sync(0xffffffffu, v, s);
        if ((threadIdx.x & 31) == 0) atomicAdd(&sh[o], v);
    }
    __syncthreads();
    if (threadIdx.x < OUTK) atomicAdd(&out[threadIdx.x], sh[threadIdx.x]);
}

// ---------------------------------------------------------------------------
extern "C" void kernel_launch(void* const* d_in, const int* in_sizes, int n_in,
                              void* d_out, int out_size)
{
    const float* F     = (const float*)d_in[0];
    const int*   src   = (const int*)d_in[1];
    const int*   dst   = (const int*)d_in[2];
    const float* gcn_w = (const float*)d_in[3];
    const float* gcn_b = (const float*)d_in[4];
    const float* fc_w  = (const float*)d_in[5];
    const float* fc_b  = (const float*)d_in[6];
    float* out = (float*)d_out;

    void* ints_addr;   cudaGetSymbolAddress(&ints_addr, g_ints);
    __half2* ha; cudaGetSymbolAddress((void**)&ha, g_ha);
    __half2* hb; cudaGetSymbolAddress((void**)&hb, g_hb);
    float*   xf; cudaGetSymbolAddress((void**)&xf, g_xf);

    // graph prep
    cudaMemsetAsync(ints_addr, 0, (2 * NN + 1) * sizeof(int));
    k_hist<<<(EE + 255) / 256, 256>>>(src, dst);
    k_build<<<(NN + 255) / 256, 256>>>(fc_b, out);
    k_scatpre<<<(NE + NH2 + 255) / 256, 256>>>(src, dst, F);

    // 3 GCN layers: ha -> hb -> ha -> xf (fp32); layer0 is the 4th launch (ncu target)
    const int lblocks = (NN + 63) / 64;
    k_layer<true ><<<lblocks, 256>>>(ha, gcn_w + 0 * DD * DD, gcn_b + 0 * DD, hb, nullptr);
    k_layer<true ><<<lblocks, 256>>>(hb, gcn_w + 1 * DD * DD, gcn_b + 1 * DD, ha, nullptr);
    k_layer<false><<<lblocks, 256>>>(ha, gcn_w + 2 * DD * DD, gcn_b + 2 * DD, nullptr, xf);

    // FC head
    k_fc<<<1563, 256>>>(fc_w, xf, out);
}